// round 1
// baseline (speedup 1.0000x reference)
#include <cuda_runtime.h>
#include <cstdint>
#include <math.h>

// ---------------- problem constants (fixed shapes) ----------------
#define BB   4
#define NX   4096
#define NY   8192
#define DD   256
#define TM   64
#define TN   64
#define NT   (NY / TN)          // 128 y tiles
#define KK   10
#define NROW (BB * NX)          // 16384
#define NVAL (NROW * KK)        // 163840
#define INV_TAU 20.0f

// normalized feature scratch (alloc-free: __device__ globals)
__device__ float g_xn[(size_t)BB * NX * DD];
__device__ float g_yn[(size_t)BB * NY * DD];

// ---------------- helpers ----------------
__device__ __forceinline__ uint32_t cvta_s(const void* p) {
    return (uint32_t)__cvta_generic_to_shared(p);
}
__device__ __forceinline__ unsigned long long lds64(uint32_t a) {
    unsigned long long v;
    asm volatile("ld.shared.b64 %0, [%1];" : "=l"(v) : "r"(a));
    return v;
}
__device__ __forceinline__ void ffma2(unsigned long long& d,
                                      unsigned long long a,
                                      unsigned long long b) {
    // packed 2x fp32 FMA (Blackwell): doubles fp32 throughput vs FFMA-3reg
    asm("fma.rn.f32x2 %0, %1, %2, %0;" : "+l"(d) : "l"(a), "l"(b));
}
__device__ __forceinline__ void cp16(uint32_t dst, const void* src) {
    asm volatile("cp.async.cg.shared.global [%0], [%1], 16;" :: "r"(dst), "l"(src));
}
__device__ __forceinline__ void cp_commit() {
    asm volatile("cp.async.commit_group;");
}
template <int N>
__device__ __forceinline__ void cp_wait() {
    asm volatile("cp.async.wait_group %0;" :: "n"(N));
}

// ---------------- kernel 1: L2 normalize rows ----------------
__global__ void norm_kernel(const float* __restrict__ fx,
                            const float* __restrict__ fy) {
    int wid  = (blockIdx.x * blockDim.x + threadIdx.x) >> 5;
    int lane = threadIdx.x & 31;
    const int total = BB * NX + BB * NY;  // 49152 rows
    if (wid >= total) return;
    const float* src;
    float* dst;
    if (wid < BB * NX) {
        src = fx + (size_t)wid * DD;
        dst = g_xn + (size_t)wid * DD;
    } else {
        int r = wid - BB * NX;
        src = fy + (size_t)r * DD;
        dst = g_yn + (size_t)r * DD;
    }
    const float4* s4 = (const float4*)src;
    float4 a = s4[lane];
    float4 b = s4[lane + 32];
    float s = a.x * a.x + a.y * a.y + a.z * a.z + a.w * a.w
            + b.x * b.x + b.y * b.y + b.z * b.z + b.w * b.w;
#pragma unroll
    for (int off = 16; off > 0; off >>= 1)
        s += __shfl_xor_sync(0xffffffffu, s, off);
    float inv = 1.0f / fmaxf(sqrtf(s), 1e-12f);
    float4* d4 = (float4*)dst;
    a.x *= inv; a.y *= inv; a.z *= inv; a.w *= inv;
    b.x *= inv; b.y *= inv; b.z *= inv; b.w *= inv;
    d4[lane]      = a;
    d4[lane + 32] = b;
}

// ---------------- kernel 2: tiled sim + fused top-k + softmax ----------------
// shared layout (bytes):
//   XS  : [0,       65536)   x tile, 64 rows x 64 float4, XOR-swizzled
//   YS  : [65536,  196608)   2 y tile buffers (double buffered)
//   SIM : [196608, 213248)   64 x 65 floats
//   LV  : [213248, 215808)   64 x 10 floats (top-k values, desc)
//   LI  : [215808, 218368)   64 x 10 ints   (top-k cols)
#define SM_XS   0
#define SM_YS   65536
#define SM_SIM  196608
#define SM_LV   213248
#define SM_LI   215808
#define SM_TOT  218368

extern __shared__ unsigned char smem_raw[];

__global__ void __launch_bounds__(256, 1)
sim_topk_kernel(float* __restrict__ out, int out_size) {
    const int b   = blockIdx.y;
    const int xt  = blockIdx.x;
    const int tid = threadIdx.x;
    const int ty  = tid >> 4;   // 0..15
    const int tx  = tid & 15;   // 0..15

    uint32_t s0   = cvta_s(smem_raw);
    float*   SIM  = (float*)(smem_raw + SM_SIM);
    float*   LV   = (float*)(smem_raw + SM_LV);
    int*     LI   = (int*)(smem_raw + SM_LI);

    // init top-k lists
    for (int i = tid; i < TM * KK; i += 256) {
        LV[i] = -1e38f;
        LI[i] = 0;
    }

    // fill X tile (64 rows x 64 float4), swizzle slot = row*64 + (q4 ^ ((row>>2)&15))
    {
        const float4* gx = (const float4*)(g_xn + ((size_t)b * NX + (size_t)xt * TM) * DD);
#pragma unroll
        for (int i = 0; i < 16; i++) {
            int f = i * 256 + tid;
            int row = f >> 6, q4 = f & 63;
            uint32_t dst = s0 + SM_XS + (uint32_t)(((row << 6) + (q4 ^ ((row >> 2) & 15))) << 4);
            cp16(dst, gx + f);
        }
    }
    // fill Y tile 0 into buffer 0
    {
        const float4* gy = (const float4*)(g_yn + (size_t)b * NY * DD);
#pragma unroll
        for (int i = 0; i < 16; i++) {
            int f = i * 256 + tid;
            int row = f >> 6, q4 = f & 63;
            uint32_t dst = s0 + SM_YS + (uint32_t)(((row << 6) + (q4 ^ ((row >> 2) & 15))) << 4);
            cp16(dst, gy + f);
        }
    }
    cp_commit();

    // per-thread row base addresses (bytes); each shared row = 1024 B
    uint32_t xrb[4], yrb0[4];
#pragma unroll
    for (int i = 0; i < 4; i++) xrb[i] = s0 + SM_XS + (uint32_t)(((ty << 2) + i) << 10);
#pragma unroll
    for (int j = 0; j < 4; j++) yrb0[j] = s0 + SM_YS + (uint32_t)(((tx << 2) + j) << 10);

    for (int t = 0; t < NT; t++) {
        // prefetch next y tile into other buffer
        if (t + 1 < NT) {
            int nxt = (t + 1) & 1;
            const float4* gy = (const float4*)(g_yn + ((size_t)b * NY + (size_t)(t + 1) * TN) * DD);
            uint32_t ybase = s0 + SM_YS + (uint32_t)(nxt * 65536);
#pragma unroll
            for (int i = 0; i < 16; i++) {
                int f = i * 256 + tid;
                int row = f >> 6, q4 = f & 63;
                uint32_t dst = ybase + (uint32_t)(((row << 6) + (q4 ^ ((row >> 2) & 15))) << 4);
                cp16(dst, gy + f);
            }
            cp_commit();
            cp_wait<1>();   // current tile's group done
        } else {
            cp_wait<0>();
        }
        __syncthreads();

        const uint32_t ybufoff = (uint32_t)((t & 1) * 65536);

        unsigned long long acc[4][4];
#pragma unroll
        for (int i = 0; i < 4; i++)
#pragma unroll
            for (int j = 0; j < 4; j++) acc[i][j] = 0ull;

#pragma unroll 4
        for (int q4 = 0; q4 < 64; q4++) {
            uint32_t ox = (uint32_t)((q4 ^ ty) << 4);
            uint32_t oy = (uint32_t)((q4 ^ tx) << 4);
            unsigned long long xl[4], xh[4], yl[4], yh[4];
#pragma unroll
            for (int i = 0; i < 4; i++) {
                xl[i] = lds64(xrb[i] + ox);
                xh[i] = lds64(xrb[i] + ox + 8);
            }
#pragma unroll
            for (int j = 0; j < 4; j++) {
                yl[j] = lds64(yrb0[j] + ybufoff + oy);
                yh[j] = lds64(yrb0[j] + ybufoff + oy + 8);
            }
#pragma unroll
            for (int i = 0; i < 4; i++)
#pragma unroll
                for (int j = 0; j < 4; j++) {
                    ffma2(acc[i][j], xl[i], yl[j]);
                    ffma2(acc[i][j], xh[i], yh[j]);
                }
        }

        // write sim tile to shared
#pragma unroll
        for (int i = 0; i < 4; i++)
#pragma unroll
            for (int j = 0; j < 4; j++) {
                float2 f = *(float2*)&acc[i][j];
                SIM[((ty << 2) + i) * 65 + (tx << 2) + j] = f.x + f.y;
            }
        __syncthreads();

        // top-k scan: one thread per x-row
        if (tid < TM) {
            float* lv = LV + tid * KK;
            int*   li = LI + tid * KK;
            const float* srow = SIM + tid * 65;
            const int col0 = t * TN;
#pragma unroll 4
            for (int c = 0; c < TN; c++) {
                float vv = srow[c];
                if (vv > lv[KK - 1]) {
                    int p = KK - 1;
                    while (p > 0 && lv[p - 1] < vv) {
                        lv[p] = lv[p - 1];
                        li[p] = li[p - 1];
                        --p;
                    }
                    lv[p] = vv;
                    li[p] = col0 + c;
                }
            }
        }
        __syncthreads();
    }

    // finalize: softmax + sort-by-col + write
    if (tid < TM) {
        float v[KK];
        int   ix[KK];
#pragma unroll
        for (int k = 0; k < KK; k++) {
            v[k]  = LV[tid * KK + k];
            ix[k] = LI[tid * KK + k];
        }
        // lists are value-descending -> max is v[0]
        float m = v[0];
        float e[KK];
        float ssum = 0.0f;
#pragma unroll
        for (int k = 0; k < KK; k++) {
            e[k] = expf((v[k] - m) * INV_TAU);
            ssum += e[k];
        }
        float inv = 1.0f / ssum;
        // insertion sort by column index ascending (indices unique)
#pragma unroll
        for (int a = 1; a < KK; a++) {
            int   ki = ix[a];
            float ke = e[a];
            int p = a;
            while (p > 0 && ix[p - 1] > ki) {
                ix[p] = ix[p - 1];
                e[p]  = e[p - 1];
                --p;
            }
            ix[p] = ki;
            e[p]  = ke;
        }
        int gRow = xt * TM + tid;
        size_t basev = ((size_t)b * NX + gRow) * KK;
        bool write_idx = (out_size >= 4 * NVAL);
#pragma unroll
        for (int k = 0; k < KK; k++) {
            out[basev + k] = e[k] * inv;
            if (write_idx) {
                out[(size_t)NVAL     + basev + k] = (float)b;
                out[(size_t)2 * NVAL + basev + k] = (float)gRow;
                out[(size_t)3 * NVAL + basev + k] = (float)ix[k];
            }
        }
    }
}

// ---------------- launch ----------------
extern "C" void kernel_launch(void* const* d_in, const int* in_sizes, int n_in,
                              void* d_out, int out_size) {
    const float* fx = (const float*)d_in[0];
    const float* fy = (const float*)d_in[1];
    float* out = (float*)d_out;

    // normalize: 49152 rows, 1 warp per row, 8 warps/block
    int nrows = BB * NX + BB * NY;
    int nblk  = (nrows + 7) / 8;
    norm_kernel<<<nblk, 256>>>(fx, fy);

    cudaFuncSetAttribute(sim_topk_kernel,
                         cudaFuncAttributeMaxDynamicSharedMemorySize, SM_TOT);
    dim3 g2(NX / TM, BB);
    sim_topk_kernel<<<g2, 256, SM_TOT>>>(out, out_size);
}

// round 3
// speedup vs baseline: 1.0776x; 1.0776x over previous
#include <cuda_runtime.h>
#include <cstdint>
#include <math.h>

// ---------------- problem constants ----------------
#define BB   4
#define NX   4096
#define NY   8192
#define DD   256
#define TM   128                 // x rows per CTA
#define TN   128                 // y cols per tile
#define KC   32                  // k per chunk
#define NT   (NY / TN)           // 64 y tiles
#define NCH  (DD / KC)           // 8 chunks per tile
#define NCC  (NT * NCH)          // 512 chunk iterations
#define KK   10
#define NROW (BB * NX)
#define NVAL (NROW * KK)         // 163840
#define INV_TAU 20.0f

// scratch: x normalized row-major, y normalized TRANSPOSED [b][k][j]
__device__ float g_xn[(size_t)BB * NX * DD];
__device__ float g_ynT[(size_t)BB * DD * NY];

// ---------------- helpers ----------------
__device__ __forceinline__ uint32_t cvta_s(const void* p) {
    return (uint32_t)__cvta_generic_to_shared(p);
}
__device__ __forceinline__ unsigned long long lds64(uint32_t a) {
    unsigned long long v;
    asm volatile("ld.shared.b64 %0, [%1];" : "=l"(v) : "r"(a));
    return v;
}
__device__ __forceinline__ float2 lds_f2(uint32_t a) {
    float2 v;
    asm volatile("ld.shared.v2.f32 {%0,%1}, [%2];" : "=f"(v.x), "=f"(v.y) : "r"(a));
    return v;
}
__device__ __forceinline__ void sts64(uint32_t a, unsigned long long v) {
    asm volatile("st.shared.b64 [%0], %1;" :: "r"(a), "l"(v));
}
__device__ __forceinline__ unsigned long long dup2(float v) {
    unsigned long long d;
    asm("mov.b64 %0, {%1,%1};" : "=l"(d) : "f"(v));
    return d;
}
__device__ __forceinline__ void ffma2(unsigned long long& d,
                                      unsigned long long a,
                                      unsigned long long b) {
    asm("fma.rn.f32x2 %0, %1, %2, %0;" : "+l"(d) : "l"(a), "l"(b));
}
__device__ __forceinline__ void cp16(uint32_t dst, const void* src) {
    asm volatile("cp.async.cg.shared.global [%0], [%1], 16;" :: "r"(dst), "l"(src));
}
__device__ __forceinline__ void cp_commit() { asm volatile("cp.async.commit_group;"); }
template <int N>
__device__ __forceinline__ void cp_wait() { asm volatile("cp.async.wait_group %0;" :: "n"(N)); }

// ---------------- kernel 1a: normalize X rows (row-major out) ----------------
__global__ void norm_x_kernel(const float* __restrict__ fx) {
    int wid  = (blockIdx.x * blockDim.x + threadIdx.x) >> 5;
    int lane = threadIdx.x & 31;
    if (wid >= BB * NX) return;
    const float4* s4 = (const float4*)(fx + (size_t)wid * DD);
    float4 a = s4[lane];
    float4 b = s4[lane + 32];
    float s = a.x*a.x + a.y*a.y + a.z*a.z + a.w*a.w
            + b.x*b.x + b.y*b.y + b.z*b.z + b.w*b.w;
#pragma unroll
    for (int off = 16; off > 0; off >>= 1) s += __shfl_xor_sync(0xffffffffu, s, off);
    float inv = 1.0f / fmaxf(sqrtf(s), 1e-12f);
    float4* d4 = (float4*)(g_xn + (size_t)wid * DD);
    a.x*=inv; a.y*=inv; a.z*=inv; a.w*=inv;
    b.x*=inv; b.y*=inv; b.z*=inv; b.w*=inv;
    d4[lane] = a;
    d4[lane + 32] = b;
}

// ---------------- kernel 1b: normalize Y rows, write TRANSPOSED ----------------
__global__ void norm_y_kernel(const float* __restrict__ fy) {
    __shared__ float buf[32 * 257];
    int blk = blockIdx.x;                  // 1024 blocks
    int b   = blk >> 8;
    int j0  = (blk & 255) * 32;
    int tid = threadIdx.x;
    int w   = tid >> 5;
    int lane = tid & 31;

#pragma unroll
    for (int rr = 0; rr < 4; rr++) {
        int row = w * 4 + rr;
        const float4* s4 = (const float4*)(fy + ((size_t)b * NY + j0 + row) * DD);
        float4 a = s4[lane];
        float4 bb = s4[lane + 32];
        float s = a.x*a.x + a.y*a.y + a.z*a.z + a.w*a.w
                + bb.x*bb.x + bb.y*bb.y + bb.z*bb.z + bb.w*bb.w;
#pragma unroll
        for (int off = 16; off > 0; off >>= 1) s += __shfl_xor_sync(0xffffffffu, s, off);
        float inv = 1.0f / fmaxf(sqrtf(s), 1e-12f);
        float* br = buf + row * 257;
        br[lane*4 + 0] = a.x * inv;  br[lane*4 + 1] = a.y * inv;
        br[lane*4 + 2] = a.z * inv;  br[lane*4 + 3] = a.w * inv;
        br[128 + lane*4 + 0] = bb.x * inv;  br[128 + lane*4 + 1] = bb.y * inv;
        br[128 + lane*4 + 2] = bb.z * inv;  br[128 + lane*4 + 3] = bb.w * inv;
    }
    __syncthreads();

#pragma unroll 8
    for (int rep = 0; rep < 32; rep++) {
        int e = rep * 256 + tid;
        int k = e >> 5;
        int j = e & 31;
        g_ynT[((size_t)b * DD + k) * NY + j0 + j] = buf[j * 257 + k];
    }
}

// ---------------- kernel 2: 128x128 tiles, f32x2 GEMM + fused top-k ----------------
// smem layout (bytes):
//   XS  [0,      131072)  x tile: 128 rows x 64 16B-units, XOR-swizzled by (row>>3)&7
//   YS  [131072, 163840)  2 x (32k x 128j) k-major y chunks
//   SIM [163840, 197120)  64 x 130 floats (half-tile staging)
//   LV  [197120, 202240)  128 x 10 floats
//   LI  [202240, 207360)  128 x 10 ints
#define SM_XS   0
#define SM_YS   131072
#define SM_SIM  163840
#define SM_LV   197120
#define SM_LI   202240
#define SM_TOT  207360
#define SIMP    130

extern __shared__ unsigned char smem_raw[];

__global__ void __launch_bounds__(256, 1)
sim_topk_kernel(float* __restrict__ out, int out_size) {
    const int b   = blockIdx.y;
    const int xt  = blockIdx.x;
    const int tid = threadIdx.x;
    const int ty  = tid >> 4;   // 0..15 -> x rows ty*8..ty*8+7
    const int tx  = tid & 15;   // y col pairs: tx+16m

    uint32_t s0  = cvta_s(smem_raw);
    float*   SIM = (float*)(smem_raw + SM_SIM);
    float*   LV  = (float*)(smem_raw + SM_LV);
    int*     LI  = (int*)(smem_raw + SM_LI);

    for (int i = tid; i < TM * KK; i += 256) { LV[i] = -1e38f; LI[i] = 0; }

    // ---- load X tile (128 x 256 floats), swizzle unit q' = q ^ ((row>>3)&7) ----
    {
        const float4* gx = (const float4*)(g_xn + ((size_t)b * NX + (size_t)xt * TM) * DD);
#pragma unroll
        for (int r = 0; r < 32; r++) {
            int idx = r * 256 + tid;           // 8192 16B units
            int i = idx >> 6, q = idx & 63;
            int qp = q ^ ((i >> 3) & 7);
            cp16(s0 + SM_XS + (uint32_t)((i << 10) + (qp << 4)), gx + idx);
        }
    }
    // ---- load y chunk 0 ----
    {
        const float* gy = g_ynT + (size_t)b * DD * NY;
#pragma unroll
        for (int r = 0; r < 4; r++) {
            int e = r * 256 + tid;             // 1024 units
            int k = e >> 5, q = e & 31;
            cp16(s0 + SM_YS + (uint32_t)((k << 9) + (q << 4)),
                 gy + (size_t)k * NY + q * 4);
        }
    }
    cp_commit();

    uint32_t xrb[8];
#pragma unroll
    for (int ii = 0; ii < 8; ii++)
        xrb[ii] = s0 + SM_XS + (uint32_t)(((ty << 3) + ii) << 10);
    uint32_t yb_pair[4];
#pragma unroll
    for (int m = 0; m < 4; m++)
        yb_pair[m] = (uint32_t)((tx + 16 * m) << 3);
    const int xsw = ty & 7;

    unsigned long long acc[8][4];

    for (int cc = 0; cc < NCC; cc++) {
        const int c = cc & 7;        // chunk within tile
        const int t = cc >> 3;       // y tile

        if (cc + 1 < NCC) {
            int cn = (cc + 1) & 7, tn = (cc + 1) >> 3;
            const float* gy = g_ynT + ((size_t)b * DD + cn * KC) * NY + (size_t)tn * TN;
            uint32_t dstb = s0 + SM_YS + (uint32_t)(((cc + 1) & 1) << 14);
#pragma unroll
            for (int r = 0; r < 4; r++) {
                int e = r * 256 + tid;
                int k = e >> 5, q = e & 31;
                cp16(dstb + (uint32_t)((k << 9) + (q << 4)), gy + (size_t)k * NY + q * 4);
            }
            cp_commit();
            cp_wait<1>();
        } else {
            cp_wait<0>();
        }
        __syncthreads();

        if (c == 0) {
#pragma unroll
            for (int ii = 0; ii < 8; ii++)
#pragma unroll
                for (int m = 0; m < 4; m++) acc[ii][m] = 0ull;
        }

        const uint32_t ybase = s0 + SM_YS + (uint32_t)((cc & 1) << 14);

        // ---- FMA over 32 k (16 pairs); X unit includes chunk base c*8 ----
#pragma unroll 4
        for (int s = 0; s < 16; s++) {
            uint32_t xoff = (uint32_t)((((c << 3) + ((s >> 1) ^ xsw)) << 4) + ((s & 1) << 3));
            float2 xv[8];
#pragma unroll
            for (int ii = 0; ii < 8; ii++) xv[ii] = lds_f2(xrb[ii] + xoff);
#pragma unroll
            for (int u = 0; u < 2; u++) {
                uint32_t yrow = ybase + (uint32_t)(((2 * s + u) << 9));
                unsigned long long yv[4];
#pragma unroll
                for (int m = 0; m < 4; m++) yv[m] = lds64(yrow + yb_pair[m]);
#pragma unroll
                for (int ii = 0; ii < 8; ii++) {
                    unsigned long long xd = dup2(u ? xv[ii].y : xv[ii].x);
#pragma unroll
                    for (int m = 0; m < 4; m++) ffma2(acc[ii][m], xd, yv[m]);
                }
            }
        }
        __syncthreads();

        // ---- tile finished: stage sim in 2 halves, update top-k ----
        if (c == 7) {
            const int col0 = t * TN;
#pragma unroll
            for (int h = 0; h < 2; h++) {
                if ((ty >> 3) == h) {
                    int rbase = (ty & 7) * 8;
#pragma unroll
                    for (int ii = 0; ii < 8; ii++) {
                        uint32_t a = s0 + SM_SIM + (uint32_t)((rbase + ii) * SIMP * 4);
#pragma unroll
                        for (int m = 0; m < 4; m++)
                            sts64(a + (uint32_t)((tx + 16 * m) << 3), acc[ii][m]);
                    }
                }
                __syncthreads();
                if (tid < 64) {
                    int row = h * 64 + tid;
                    float* lv = LV + row * KK;
                    int*   li = LI + row * KK;
                    const float* srow = SIM + tid * SIMP;
                    float lv9 = lv[KK - 1];
#pragma unroll 4
                    for (int cL = 0; cL < TN; cL++) {
                        float vv = srow[cL];
                        if (vv > lv9) {
                            int p = KK - 1;
                            while (p > 0 && lv[p - 1] < vv) {
                                lv[p] = lv[p - 1]; li[p] = li[p - 1]; --p;
                            }
                            lv[p] = vv; li[p] = col0 + cL;
                            lv9 = lv[KK - 1];
                        }
                    }
                }
                __syncthreads();
            }
        }
    }

    // ---- finalize: softmax + sort-by-col + write ----
    if (tid < TM) {
        float v[KK]; int ix[KK];
#pragma unroll
        for (int k = 0; k < KK; k++) { v[k] = LV[tid * KK + k]; ix[k] = LI[tid * KK + k]; }
        float m = v[0];
        float e[KK]; float ssum = 0.0f;
#pragma unroll
        for (int k = 0; k < KK; k++) { e[k] = expf((v[k] - m) * INV_TAU); ssum += e[k]; }
        float inv = 1.0f / ssum;
#pragma unroll
        for (int a = 1; a < KK; a++) {
            int ki = ix[a]; float ke = e[a]; int p = a;
            while (p > 0 && ix[p - 1] > ki) { ix[p] = ix[p - 1]; e[p] = e[p - 1]; --p; }
            ix[p] = ki; e[p] = ke;
        }
        int gRow = xt * TM + tid;
        size_t basev = ((size_t)b * NX + gRow) * KK;
        bool write_idx = (out_size >= 4 * NVAL);
#pragma unroll
        for (int k = 0; k < KK; k++) {
            out[basev + k] = e[k] * inv;
            if (write_idx) {
                out[(size_t)NVAL     + basev + k] = (float)b;
                out[(size_t)2 * NVAL + basev + k] = (float)gRow;
                out[(size_t)3 * NVAL + basev + k] = (float)ix[k];
            }
        }
    }
}

// ---------------- launch ----------------
extern "C" void kernel_launch(void* const* d_in, const int* in_sizes, int n_in,
                              void* d_out, int out_size) {
    const float* fx = (const float*)d_in[0];
    const float* fy = (const float*)d_in[1];
    float* out = (float*)d_out;

    norm_x_kernel<<<(BB * NX) / 8, 256>>>(fx);
    norm_y_kernel<<<(BB * NY) / 32, 256>>>(fy);

    cudaFuncSetAttribute(sim_topk_kernel,
                         cudaFuncAttributeMaxDynamicSharedMemorySize, SM_TOT);
    dim3 g2(NX / TM, BB);                            // 128 CTAs
    sim_topk_kernel<<<g2, 256, SM_TOT>>>(out, out_size);
}